// round 8
// baseline (speedup 1.0000x reference)
#include <cuda_runtime.h>
#include <cuda_fp16.h>
#include <cstdint>

#define B_  4096
#define N_  49
#define H_  8
#define NW_ 64
#define MT  (B_ * N_)              // 200704 rows
#define KSP 512                    // 2-term split K (2 * 256)
#define SZ_AO ((size_t)MT * 256)
#define NN2 (N_ * N_)              // 2401

#define SCALE_F 0.17677669529663687f

// ---------------- scratch (device globals; no runtime alloc) ----------------
__device__ __half g_A[2][(size_t)MT * KSP];     // input split [hi, lo] fp16
__device__ __half g_Wqkv[2][768 * 256];         // Wt[n][k] fp16
__device__ __half g_Wproj[2][256 * 256];
__device__ float  g_lin[2][(size_t)MT * 768];   // qkv linear out (q|k|v)
__device__ __half g_aob[2][(size_t)MT * KSP];   // attn out split [hi, lo]
__device__ float  g_bm[NW_ * H_ * NN2];         // combined bias+mask

// ---------------- GEMM config ----------------
#define BM 128
#define BN 256
#define KCH 64                      // k elems per chunk
#define NCHUNK (KSP / KCH)          // 8
#define SA_STR 72                   // 64 + 8 pad
#define SB_STR 264                  // 256 + 8 pad
#define NTHR 512

struct GSmem {
    __align__(16) __half B[BN * SB_STR];        // 135168 B
    __align__(16) __half A[3][BM * SA_STR];     // 3 x 18432 B
};
#define SMEM_SZ ((int)sizeof(GSmem))

__device__ __forceinline__ void cp16(uint32_t dst, const void* src) {
    asm volatile("cp.async.cg.shared.global [%0], [%1], 16;" :: "r"(dst), "l"(src));
}
__device__ __forceinline__ void cp_commit() {
    asm volatile("cp.async.commit_group;" ::: "memory");
}
template<int NN> __device__ __forceinline__ void cp_wait() {
    asm volatile("cp.async.wait_group %0;" :: "n"(NN) : "memory");
}

__device__ __forceinline__ void mma16816(float* d, const uint32_t* a, const uint32_t* b) {
    asm volatile(
        "mma.sync.aligned.m16n8k16.row.col.f32.f16.f16.f32 "
        "{%0,%1,%2,%3}, {%4,%5,%6,%7}, {%8,%9}, {%0,%1,%2,%3};"
        : "+f"(d[0]), "+f"(d[1]), "+f"(d[2]), "+f"(d[3])
        : "r"(a[0]), "r"(a[1]), "r"(a[2]), "r"(a[3]), "r"(b[0]), "r"(b[1]));
}

#define LDSM_X4(r, addr)                                                     \
    asm volatile("ldmatrix.sync.aligned.m8n8.x4.shared.b16 {%0,%1,%2,%3}, [%4];" \
        : "=r"((r)[0]), "=r"((r)[1]), "=r"((r)[2]), "=r"((r)[3]) : "r"(addr))

// GEMM mainloop: D[128,256] tile at (bm, bn). 512 threads, warp grid 2(M)x8(N),
// warp tile 64x32. B panel resident; A 3-stage K=64 pipeline.
__device__ __forceinline__ void gemm_main(
    GSmem& sm, const __half* __restrict__ A, const __half* __restrict__ W,
    int bm, int bn, float acc[4][4][4])
{
    const int tid = threadIdx.x;
    const uint32_t sB = (uint32_t)__cvta_generic_to_shared(sm.B);
    const uint32_t sA = (uint32_t)__cvta_generic_to_shared(sm.A);

    // B panel: 256 rows x 256 halves (8192 cp16, 16/thread)
    #pragma unroll
    for (int i = 0; i < 16; i++) {
        int idx = tid + i * NTHR;
        int r = idx >> 5, g = idx & 31;
        cp16(sB + (uint32_t)(r * SB_STR + g * 8) * 2,
             W + (size_t)(bn + r) * 256 + g * 8);
    }
    cp_commit();

    auto issueA = [&](int c) {
        uint32_t dst = sA + (uint32_t)((c % 3) * BM * SA_STR) * 2;
        // 128 rows x 8 groups of 8 halves = 1024 cp16, 2/thread
        #pragma unroll
        for (int i = 0; i < 2; i++) {
            int idx = tid + i * NTHR;
            int r = idx >> 3, g = idx & 7;
            cp16(dst + (uint32_t)(r * SA_STR + g * 8) * 2,
                 A + (size_t)(bm + r) * KSP + c * KCH + g * 8);
        }
        cp_commit();
    };
    issueA(0); issueA(1);

    const int lane = tid & 31;
    const int wm = (tid >> 5) & 1;      // 2 warps along M
    const int wn = tid >> 6;            // 8 warps along N

    const int a_row = wm * 64 + (lane & 7) + ((lane >> 3) & 1) * 8;  // + mt*16
    const int a_col = (lane >> 4) * 8;                                // + kb
    const int b_row = wn * 32 + (lane >> 4) * 8 + (lane & 7);         // + pair*16
    const int b_col = ((lane >> 3) & 1) * 8;                          // + kb

    auto compute = [&](int c) {
        const uint32_t aBase = sA + (uint32_t)((c % 3) * BM * SA_STR) * 2;
        const uint32_t bBase = sB + (uint32_t)((c & 3) * KCH) * 2;
        #pragma unroll
        for (int ks = 0; ks < 4; ks++) {
            const int kb = ks * 16;
            uint32_t af[4][4], bf[2][4];
            #pragma unroll
            for (int mt = 0; mt < 4; mt++)
                LDSM_X4(af[mt],
                        aBase + (uint32_t)((a_row + mt * 16) * SA_STR + kb + a_col) * 2);
            #pragma unroll
            for (int pr = 0; pr < 2; pr++)
                LDSM_X4(bf[pr],
                        bBase + (uint32_t)((b_row + pr * 16) * SB_STR + kb + b_col) * 2);
            #pragma unroll
            for (int mt = 0; mt < 4; mt++)
                #pragma unroll
                for (int nt = 0; nt < 4; nt++)
                    mma16816(acc[mt][nt], af[mt], &bf[nt >> 1][(nt & 1) * 2]);
        }
    };

    for (int c = 0; c < NCHUNK - 1; c++) {
        cp_wait<1>();           // stage c arrived (A[c+1] may be in flight)
        __syncthreads();        // all warps done with compute(c-1) -> stage (c+2)%3 free
        if (c + 2 < NCHUNK) issueA(c + 2);
        compute(c);
    }
    cp_wait<0>();
    __syncthreads();
    compute(NCHUNK - 1);
}

// ---------------- GEMM kernels ----------------
__global__ __launch_bounds__(NTHR, 1) void qkv_hmma(
    const float* __restrict__ b0, const float* __restrict__ b1)
{
    extern __shared__ char smem_raw[];
    GSmem& sm = *(GSmem*)smem_raw;
    const int stream = blockIdx.z;
    const int bn = blockIdx.x * BN;
    const int bm = blockIdx.y * BM;

    float acc[4][4][4] = {};
    gemm_main(sm, g_A[stream], g_Wqkv[stream], bm, bn, acc);

    const float* __restrict__ bias = stream ? b1 : b0;
    float* __restrict__ O = g_lin[stream];
    const int lane = threadIdx.x & 31;
    const int wm = (threadIdx.x >> 5) & 1, wn = threadIdx.x >> 6;
    const float sc = (bn == 0) ? SCALE_F : 1.0f;   // BN=256 aligns with q|k|v segments

    #pragma unroll
    for (int mt = 0; mt < 4; mt++) {
        const int r = bm + wm * 64 + mt * 16 + (lane >> 2);
        #pragma unroll
        for (int nt = 0; nt < 4; nt++) {
            const int col = bn + wn * 32 + nt * 8 + (lane & 3) * 2;
            const float bx = bias[col], by = bias[col + 1];
            float2 v0 = { (acc[mt][nt][0] + bx) * sc, (acc[mt][nt][1] + by) * sc };
            float2 v1 = { (acc[mt][nt][2] + bx) * sc, (acc[mt][nt][3] + by) * sc };
            *(float2*)&O[(size_t)r * 768 + col]       = v0;
            *(float2*)&O[(size_t)(r + 8) * 768 + col] = v1;
        }
    }
}

__global__ __launch_bounds__(NTHR, 1) void proj_hmma(
    const float* __restrict__ bp0, const float* __restrict__ bp1,
    float* __restrict__ out)
{
    extern __shared__ char smem_raw[];
    GSmem& sm = *(GSmem*)smem_raw;
    const int p = blockIdx.z;
    const int bm = blockIdx.y * BM;

    float acc[4][4][4] = {};
    gemm_main(sm, g_aob[p], g_Wproj[p], bm, 0, acc);

    const float* __restrict__ bias = p ? bp1 : bp0;
    float* __restrict__ O = out + (size_t)p * SZ_AO;
    const int lane = threadIdx.x & 31;
    const int wm = (threadIdx.x >> 5) & 1, wn = threadIdx.x >> 6;

    #pragma unroll
    for (int mt = 0; mt < 4; mt++) {
        const int r = bm + wm * 64 + mt * 16 + (lane >> 2);
        #pragma unroll
        for (int nt = 0; nt < 4; nt++) {
            const int col = wn * 32 + nt * 8 + (lane & 3) * 2;
            const float bx = bias[col], by = bias[col + 1];
            float2 v0 = { acc[mt][nt][0] + bx, acc[mt][nt][1] + by };
            float2 v1 = { acc[mt][nt][2] + bx, acc[mt][nt][3] + by };
            *(float2*)&O[(size_t)r * 256 + col]       = v0;
            *(float2*)&O[(size_t)(r + 8) * 256 + col] = v1;
        }
    }
}

// ---------------- conversion / precompute kernels ----------------
__global__ __launch_bounds__(256) void conv_in(
    const float* __restrict__ x, const float* __restrict__ rgb)
{
    const int s = blockIdx.y;
    const float* __restrict__ src = s ? rgb : x;
    const size_t m = blockIdx.x;
    const int k = threadIdx.x;
    float v = src[m * 256 + k];
    __half hi = __float2half_rn(v);
    __half lo = __float2half_rn(v - __half2float(hi));
    g_A[s][m * KSP + k] = hi;
    g_A[s][m * KSP + 256 + k] = lo;
}

__global__ __launch_bounds__(256) void conv_w(
    const float* __restrict__ w_qkv, const float* __restrict__ w_qkv_rgb,
    const float* __restrict__ w_proj, const float* __restrict__ w_proj_rgb)
{
    const int which = blockIdx.y;
    const float* src; __half* dst; int NC;
    switch (which) {
        case 0: src = w_qkv;       dst = g_Wqkv[0];  NC = 768; break;
        case 1: src = w_qkv_rgb;   dst = g_Wqkv[1];  NC = 768; break;
        case 2: src = w_proj;      dst = g_Wproj[0]; NC = 256; break;
        default: src = w_proj_rgb; dst = g_Wproj[1]; NC = 256; break;
    }
    int idx = blockIdx.x * 256 + threadIdx.x;
    if (idx >= 256 * NC) return;
    int k = idx / NC, n = idx % NC;
    dst[(size_t)n * 256 + k] = __float2half_rn(src[idx]);
}

__global__ __launch_bounds__(256) void prep_bm(
    const float* __restrict__ mask, const float* __restrict__ bias_table,
    const int* __restrict__ rel_idx)
{
    const int w = blockIdx.x, h = blockIdx.y;
    float* __restrict__ dst = g_bm + (size_t)(w * H_ + h) * NN2;
    const float* __restrict__ msk = mask + (size_t)w * NN2;
    for (int idx = threadIdx.x; idx < NN2; idx += 256)
        dst[idx] = bias_table[rel_idx[idx] * H_ + h] + msk[idx];
}

// ---------------- fused attention (fp32, register-blocked) ----------------
__global__ __launch_bounds__(192) void attn_kernel()
{
    const int b = blockIdx.x, h = blockIdx.y, p = blockIdx.z;
    const int qs = p ^ 1, kv = p;
    const float* __restrict__ qb = g_lin[qs] + (size_t)b * N_ * 768 + h * 32;
    const float* __restrict__ kb = g_lin[kv] + (size_t)b * N_ * 768 + 256 + h * 32;
    const float* __restrict__ vb = g_lin[kv] + (size_t)b * N_ * 768 + 512 + h * 32;
    const float* __restrict__ bm = g_bm + (size_t)((b & (NW_ - 1)) * H_ + h) * NN2;

    __shared__ float qT[32 * 56];   // [d][n]
    __shared__ float kT[32 * 56];
    __shared__ float V[N_ * 36];    // [n][d]
    __shared__ float S[52 * 56];    // padded: PV tile reads rows 49-51

    const int tid = threadIdx.x;
    for (int i = tid; i < N_ * 32; i += 192) {
        int n = i >> 5, d = i & 31;
        qT[d * 56 + n] = qb[n * 768 + d];
        kT[d * 56 + n] = kb[n * 768 + d];
        V[n * 36 + d]  = vb[n * 768 + d];
    }
    for (int i = tid; i < 3 * 56; i += 192) S[49 * 56 + i] = 0.f;
    __syncthreads();

    if (tid < 169) {
        const int it = tid / 13, jt = tid - (tid / 13) * 13;
        const int i0 = it * 4, j0 = jt * 4;
        float acc[4][4] = {};
        #pragma unroll
        for (int d = 0; d < 32; d++) {
            float4 a  = *(const float4*)&qT[d * 56 + i0];
            float4 bb = *(const float4*)&kT[d * 56 + j0];
            float ar[4] = {a.x, a.y, a.z, a.w};
            float br[4] = {bb.x, bb.y, bb.z, bb.w};
            #pragma unroll
            for (int r = 0; r < 4; r++)
                #pragma unroll
                for (int c = 0; c < 4; c++)
                    acc[r][c] += ar[r] * br[c];
        }
        #pragma unroll
        for (int r = 0; r < 4; r++) {
            int i = i0 + r;
            if (i >= N_) break;
            #pragma unroll
            for (int c = 0; c < 4; c++) {
                int j = j0 + c;
                if (j >= N_) continue;
                S[i * 56 + j] = acc[r][c] + bm[i * N_ + j];
            }
        }
    }
    __syncthreads();

    {
        const int w = tid >> 5, lane = tid & 31;
        for (int r = w; r < N_; r += 6) {
            float* row = &S[r * 56];
            float v1 = row[lane];
            float v2 = (lane + 32 < N_) ? row[lane + 32] : -1e30f;
            float mx = fmaxf(v1, v2);
            #pragma unroll
            for (int o = 16; o; o >>= 1) mx = fmaxf(mx, __shfl_xor_sync(~0u, mx, o));
            float e1 = __expf(v1 - mx);
            float e2 = (lane + 32 < N_) ? __expf(v2 - mx) : 0.f;
            float s = e1 + e2;
            #pragma unroll
            for (int o = 16; o; o >>= 1) s += __shfl_xor_sync(~0u, s, o);
            float inv = 1.f / s;
            row[lane] = e1 * inv;
            if (lane + 32 < N_) row[lane + 32] = e2 * inv;
        }
    }
    __syncthreads();

    for (int t = tid; t < 208; t += 192) {
        const int it = t >> 4, dt = t & 15;
        const int i0 = it * 4, d0 = dt * 2;
        float o[4][2] = {};
        for (int j = 0; j < N_; j++) {
            float2 vv = *(const float2*)&V[j * 36 + d0];
            #pragma unroll
            for (int r = 0; r < 4; r++) {
                float pr = S[(i0 + r) * 56 + j];
                o[r][0] += pr * vv.x;
                o[r][1] += pr * vv.y;
            }
        }
        #pragma unroll
        for (int r = 0; r < 4; r++) {
            int i = i0 + r;
            if (i >= N_) break;
            __half* dst = &g_aob[p][((size_t)b * N_ + i) * KSP + h * 32 + d0];
            __half h0 = __float2half_rn(o[r][0]);
            __half h1 = __float2half_rn(o[r][1]);
            __half l0 = __float2half_rn(o[r][0] - __half2float(h0));
            __half l1 = __float2half_rn(o[r][1] - __half2float(h1));
            *(__half2*)dst         = __halves2half2(h0, h1);
            *(__half2*)(dst + 256) = __halves2half2(l0, l1);
        }
    }
}

// ---------------- host launcher ----------------
extern "C" void kernel_launch(void* const* d_in, const int* in_sizes, int n_in,
                              void* d_out, int out_size)
{
    const float* x          = (const float*)d_in[0];
    const float* rgb        = (const float*)d_in[1];
    const float* mask       = (const float*)d_in[2];
    const float* w_qkv      = (const float*)d_in[3];
    const float* b_qkv      = (const float*)d_in[4];
    const float* w_qkv_rgb  = (const float*)d_in[5];
    const float* b_qkv_rgb  = (const float*)d_in[6];
    const float* bias_table = (const float*)d_in[7];
    const float* w_proj     = (const float*)d_in[8];
    const float* b_proj     = (const float*)d_in[9];
    const float* w_proj_rgb = (const float*)d_in[10];
    const float* b_proj_rgb = (const float*)d_in[11];
    const int*   rel_idx    = (const int*)d_in[12];
    float* out = (float*)d_out;

    cudaFuncSetAttribute(qkv_hmma,  cudaFuncAttributeMaxDynamicSharedMemorySize, SMEM_SZ);
    cudaFuncSetAttribute(proj_hmma, cudaFuncAttributeMaxDynamicSharedMemorySize, SMEM_SZ);

    conv_w<<<dim3(768, 4), 256>>>(w_qkv, w_qkv_rgb, w_proj, w_proj_rgb);
    prep_bm<<<dim3(NW_, H_), 256>>>(mask, bias_table, rel_idx);
    conv_in<<<dim3(MT, 2), 256>>>(x, rgb);

    qkv_hmma<<<dim3(768 / BN, MT / BM, 2), NTHR, SMEM_SZ>>>(b_qkv, b_qkv_rgb);

    attn_kernel<<<dim3(B_, H_, 2), 192>>>();

    proj_hmma<<<dim3(1, MT / BM, 2), NTHR, SMEM_SZ>>>(b_proj, b_proj_rgb, out);
}

// round 9
// speedup vs baseline: 1.0181x; 1.0181x over previous
#include <cuda_runtime.h>
#include <cuda_fp16.h>
#include <cstdint>

#define B_  4096
#define N_  49
#define H_  8
#define NW_ 64
#define MT  (B_ * N_)              // 200704 rows
#define KSP 512                    // 2-term split K (2 * 256)
#define SZ_AO ((size_t)MT * 256)
#define NN2 (N_ * N_)              // 2401

#define SCALE_F 0.17677669529663687f

// ---------------- scratch (device globals; no runtime alloc) ----------------
__device__ __half g_A[2][(size_t)MT * KSP];     // input split [hi, lo] fp16
__device__ __half g_Wqkv[2][768 * 256];         // Wt[n][k] fp16
__device__ __half g_Wproj[2][256 * 256];
__device__ float  g_lin[2][(size_t)MT * 768];   // qkv linear out (q|k|v)
__device__ __half g_aob[2][(size_t)MT * KSP];   // attn out split [hi, lo]
__device__ float  g_bm[NW_ * H_ * NN2];         // combined bias+mask

// ---------------- GEMM config ----------------
#define BM 128
#define BN 128
#define KCH 64                      // k elems per chunk
#define NCHUNK (KSP / KCH)          // 8
#define STR 72                      // halves per smem row (64 + 8 pad)

struct GSmem {
    __align__(16) __half A[3][BM * STR];        // 3 x 18432 B
    __align__(16) __half B[3][BN * STR];        // 3 x 18432 B
};
#define SMEM_SZ ((int)sizeof(GSmem))            // 110592

__device__ __forceinline__ void cp16(uint32_t dst, const void* src) {
    asm volatile("cp.async.cg.shared.global [%0], [%1], 16;" :: "r"(dst), "l"(src));
}
__device__ __forceinline__ void cp_commit() {
    asm volatile("cp.async.commit_group;" ::: "memory");
}
template<int NN> __device__ __forceinline__ void cp_wait() {
    asm volatile("cp.async.wait_group %0;" :: "n"(NN) : "memory");
}

__device__ __forceinline__ void mma16816(float* d, const uint32_t* a, const uint32_t* b) {
    asm volatile(
        "mma.sync.aligned.m16n8k16.row.col.f32.f16.f16.f32 "
        "{%0,%1,%2,%3}, {%4,%5,%6,%7}, {%8,%9}, {%0,%1,%2,%3};"
        : "+f"(d[0]), "+f"(d[1]), "+f"(d[2]), "+f"(d[3])
        : "r"(a[0]), "r"(a[1]), "r"(a[2]), "r"(a[3]), "r"(b[0]), "r"(b[1]));
}

#define LDSM_X4(r, addr)                                                     \
    asm volatile("ldmatrix.sync.aligned.m8n8.x4.shared.b16 {%0,%1,%2,%3}, [%4];" \
        : "=r"((r)[0]), "=r"((r)[1]), "=r"((r)[2]), "=r"((r)[3]) : "r"(addr))

// GEMM mainloop: D[128,128] tile at (bm, bn). 256 threads, warp grid 2(M)x4(N),
// warp tile 64x32. A and B both 3-stage cp.async pipelined, K-chunk 64.
__device__ __forceinline__ void gemm_main(
    GSmem& sm, const __half* __restrict__ A, const __half* __restrict__ W,
    int bm, int bn, float acc[4][4][4])
{
    const int tid = threadIdx.x;
    const uint32_t sA = (uint32_t)__cvta_generic_to_shared(sm.A);
    const uint32_t sB = (uint32_t)__cvta_generic_to_shared(sm.B);

    auto issueAB = [&](int c) {
        const int s = c % 3;
        uint32_t dstA = sA + (uint32_t)(s * BM * STR) * 2;
        uint32_t dstB = sB + (uint32_t)(s * BN * STR) * 2;
        const int k0 = c * KCH;
        #pragma unroll
        for (int i = 0; i < 4; i++) {
            int idx = tid + i * 256;        // 0..1023
            int r = idx >> 3, g = idx & 7;  // 128 rows x 8 groups
            cp16(dstA + (uint32_t)(r * STR + g * 8) * 2,
                 A + (size_t)(bm + r) * KSP + k0 + g * 8);
            cp16(dstB + (uint32_t)(r * STR + g * 8) * 2,
                 W + (size_t)(bn + r) * 256 + k0 + g * 8);
        }
        cp_commit();
    };
    issueAB(0); issueAB(1);

    const int lane = tid & 31;
    const int wm = (tid >> 5) & 1;      // 2 warps along M
    const int wn = tid >> 6;            // 4 warps along N

    const int a_row = wm * 64 + (lane & 7) + ((lane >> 3) & 1) * 8;  // + mt*16
    const int a_col = (lane >> 4) * 8;                                // + kb
    const int b_row = wn * 32 + (lane >> 4) * 8 + (lane & 7);         // + pair*16
    const int b_col = ((lane >> 3) & 1) * 8;                          // + kb

    auto compute = [&](int c) {
        const int s = c % 3;
        const uint32_t aBase = sA + (uint32_t)(s * BM * STR) * 2;
        const uint32_t bBase = sB + (uint32_t)(s * BN * STR) * 2;
        #pragma unroll
        for (int ks = 0; ks < 4; ks++) {
            const int kb = ks * 16;
            uint32_t af[4][4], bf[2][4];
            #pragma unroll
            for (int mt = 0; mt < 4; mt++)
                LDSM_X4(af[mt],
                        aBase + (uint32_t)((a_row + mt * 16) * STR + kb + a_col) * 2);
            #pragma unroll
            for (int pr = 0; pr < 2; pr++)
                LDSM_X4(bf[pr],
                        bBase + (uint32_t)((b_row + pr * 16) * STR + kb + b_col) * 2);
            #pragma unroll
            for (int mt = 0; mt < 4; mt++)
                #pragma unroll
                for (int nt = 0; nt < 4; nt++)
                    mma16816(acc[mt][nt], af[mt], &bf[nt >> 1][(nt & 1) * 2]);
        }
    };

    for (int c = 0; c < NCHUNK - 2; c++) {
        cp_wait<1>();
        __syncthreads();        // stage (c-1)%3 free for reuse
        issueAB(c + 2);
        compute(c);
    }
    cp_wait<1>(); __syncthreads(); compute(NCHUNK - 2);
    cp_wait<0>(); __syncthreads(); compute(NCHUNK - 1);
}

// ---------------- GEMM kernels ----------------
__global__ __launch_bounds__(256, 2) void qkv_hmma(
    const float* __restrict__ b0, const float* __restrict__ b1)
{
    extern __shared__ char smem_raw[];
    GSmem& sm = *(GSmem*)smem_raw;
    const int stream = blockIdx.z;
    const int bn = blockIdx.x * BN;
    const int bm = blockIdx.y * BM;

    float acc[4][4][4] = {};
    gemm_main(sm, g_A[stream], g_Wqkv[stream], bm, bn, acc);

    const float* __restrict__ bias = stream ? b1 : b0;
    float* __restrict__ O = g_lin[stream];
    const int lane = threadIdx.x & 31;
    const int wm = (threadIdx.x >> 5) & 1, wn = threadIdx.x >> 6;
    const float sc = (bn < 256) ? SCALE_F : 1.0f;

    #pragma unroll
    for (int mt = 0; mt < 4; mt++) {
        const int r = bm + wm * 64 + mt * 16 + (lane >> 2);
        #pragma unroll
        for (int nt = 0; nt < 4; nt++) {
            const int col = bn + wn * 32 + nt * 8 + (lane & 3) * 2;
            const float bx = bias[col], by = bias[col + 1];
            float2 v0 = { (acc[mt][nt][0] + bx) * sc, (acc[mt][nt][1] + by) * sc };
            float2 v1 = { (acc[mt][nt][2] + bx) * sc, (acc[mt][nt][3] + by) * sc };
            *(float2*)&O[(size_t)r * 768 + col]       = v0;
            *(float2*)&O[(size_t)(r + 8) * 768 + col] = v1;
        }
    }
}

__global__ __launch_bounds__(256, 2) void proj_hmma(
    const float* __restrict__ bp0, const float* __restrict__ bp1,
    float* __restrict__ out)
{
    extern __shared__ char smem_raw[];
    GSmem& sm = *(GSmem*)smem_raw;
    const int p = blockIdx.z;
    const int bn = blockIdx.x * BN;
    const int bm = blockIdx.y * BM;

    float acc[4][4][4] = {};
    gemm_main(sm, g_aob[p], g_Wproj[p], bm, bn, acc);

    const float* __restrict__ bias = p ? bp1 : bp0;
    float* __restrict__ O = out + (size_t)p * SZ_AO;
    const int lane = threadIdx.x & 31;
    const int wm = (threadIdx.x >> 5) & 1, wn = threadIdx.x >> 6;

    #pragma unroll
    for (int mt = 0; mt < 4; mt++) {
        const int r = bm + wm * 64 + mt * 16 + (lane >> 2);
        #pragma unroll
        for (int nt = 0; nt < 4; nt++) {
            const int col = bn + wn * 32 + nt * 8 + (lane & 3) * 2;
            const float bx = bias[col], by = bias[col + 1];
            float2 v0 = { acc[mt][nt][0] + bx, acc[mt][nt][1] + by };
            float2 v1 = { acc[mt][nt][2] + bx, acc[mt][nt][3] + by };
            *(float2*)&O[(size_t)r * 256 + col]       = v0;
            *(float2*)&O[(size_t)(r + 8) * 256 + col] = v1;
        }
    }
}

// ---------------- conversion / precompute kernels ----------------
__global__ __launch_bounds__(256) void conv_in(
    const float* __restrict__ x, const float* __restrict__ rgb)
{
    const int s = blockIdx.y;
    const float* __restrict__ src = s ? rgb : x;
    const size_t m = blockIdx.x;
    const int k = threadIdx.x;
    float v = src[m * 256 + k];
    __half hi = __float2half_rn(v);
    __half lo = __float2half_rn(v - __half2float(hi));
    g_A[s][m * KSP + k] = hi;
    g_A[s][m * KSP + 256 + k] = lo;
}

__global__ __launch_bounds__(256) void conv_w(
    const float* __restrict__ w_qkv, const float* __restrict__ w_qkv_rgb,
    const float* __restrict__ w_proj, const float* __restrict__ w_proj_rgb)
{
    const int which = blockIdx.y;
    const float* src; __half* dst; int NC;
    switch (which) {
        case 0: src = w_qkv;       dst = g_Wqkv[0];  NC = 768; break;
        case 1: src = w_qkv_rgb;   dst = g_Wqkv[1];  NC = 768; break;
        case 2: src = w_proj;      dst = g_Wproj[0]; NC = 256; break;
        default: src = w_proj_rgb; dst = g_Wproj[1]; NC = 256; break;
    }
    int idx = blockIdx.x * 256 + threadIdx.x;
    if (idx >= 256 * NC) return;
    int k = idx / NC, n = idx % NC;
    dst[(size_t)n * 256 + k] = __float2half_rn(src[idx]);
}

__global__ __launch_bounds__(256) void prep_bm(
    const float* __restrict__ mask, const float* __restrict__ bias_table,
    const int* __restrict__ rel_idx)
{
    const int w = blockIdx.x, h = blockIdx.y;
    float* __restrict__ dst = g_bm + (size_t)(w * H_ + h) * NN2;
    const float* __restrict__ msk = mask + (size_t)w * NN2;
    for (int idx = threadIdx.x; idx < NN2; idx += 256)
        dst[idx] = bias_table[rel_idx[idx] * H_ + h] + msk[idx];
}

// ---------------- fused attention (fp32, register-blocked) ----------------
__global__ __launch_bounds__(192) void attn_kernel()
{
    const int b = blockIdx.x, h = blockIdx.y, p = blockIdx.z;
    const int qs = p ^ 1, kv = p;
    const float* __restrict__ qb = g_lin[qs] + (size_t)b * N_ * 768 + h * 32;
    const float* __restrict__ kb = g_lin[kv] + (size_t)b * N_ * 768 + 256 + h * 32;
    const float* __restrict__ vb = g_lin[kv] + (size_t)b * N_ * 768 + 512 + h * 32;
    const float* __restrict__ bm = g_bm + (size_t)((b & (NW_ - 1)) * H_ + h) * NN2;

    __shared__ float qT[32 * 56];   // [d][n]
    __shared__ float kT[32 * 56];
    __shared__ float V[N_ * 36];    // [n][d]
    __shared__ float S[52 * 56];    // padded: PV tile reads rows 49-51

    const int tid = threadIdx.x;
    for (int i = tid; i < N_ * 32; i += 192) {
        int n = i >> 5, d = i & 31;
        qT[d * 56 + n] = qb[n * 768 + d];
        kT[d * 56 + n] = kb[n * 768 + d];
        V[n * 36 + d]  = vb[n * 768 + d];
    }
    for (int i = tid; i < 3 * 56; i += 192) S[49 * 56 + i] = 0.f;
    __syncthreads();

    if (tid < 169) {
        const int it = tid / 13, jt = tid - (tid / 13) * 13;
        const int i0 = it * 4, j0 = jt * 4;
        float acc[4][4] = {};
        #pragma unroll
        for (int d = 0; d < 32; d++) {
            float4 a  = *(const float4*)&qT[d * 56 + i0];
            float4 bb = *(const float4*)&kT[d * 56 + j0];
            float ar[4] = {a.x, a.y, a.z, a.w};
            float br[4] = {bb.x, bb.y, bb.z, bb.w};
            #pragma unroll
            for (int r = 0; r < 4; r++)
                #pragma unroll
                for (int c = 0; c < 4; c++)
                    acc[r][c] += ar[r] * br[c];
        }
        #pragma unroll
        for (int r = 0; r < 4; r++) {
            int i = i0 + r;
            if (i >= N_) break;
            #pragma unroll
            for (int c = 0; c < 4; c++) {
                int j = j0 + c;
                if (j >= N_) continue;
                S[i * 56 + j] = acc[r][c] + bm[i * N_ + j];
            }
        }
    }
    __syncthreads();

    {
        const int w = tid >> 5, lane = tid & 31;
        for (int r = w; r < N_; r += 6) {
            float* row = &S[r * 56];
            float v1 = row[lane];
            float v2 = (lane + 32 < N_) ? row[lane + 32] : -1e30f;
            float mx = fmaxf(v1, v2);
            #pragma unroll
            for (int o = 16; o; o >>= 1) mx = fmaxf(mx, __shfl_xor_sync(~0u, mx, o));
            float e1 = __expf(v1 - mx);
            float e2 = (lane + 32 < N_) ? __expf(v2 - mx) : 0.f;
            float s = e1 + e2;
            #pragma unroll
            for (int o = 16; o; o >>= 1) s += __shfl_xor_sync(~0u, s, o);
            float inv = 1.f / s;
            row[lane] = e1 * inv;
            if (lane + 32 < N_) row[lane + 32] = e2 * inv;
        }
    }
    __syncthreads();

    for (int t = tid; t < 208; t += 192) {
        const int it = t >> 4, dt = t & 15;
        const int i0 = it * 4, d0 = dt * 2;
        float o[4][2] = {};
        for (int j = 0; j < N_; j++) {
            float2 vv = *(const float2*)&V[j * 36 + d0];
            #pragma unroll
            for (int r = 0; r < 4; r++) {
                float pr = S[(i0 + r) * 56 + j];
                o[r][0] += pr * vv.x;
                o[r][1] += pr * vv.y;
            }
        }
        #pragma unroll
        for (int r = 0; r < 4; r++) {
            int i = i0 + r;
            if (i >= N_) break;
            __half* dst = &g_aob[p][((size_t)b * N_ + i) * KSP + h * 32 + d0];
            __half h0 = __float2half_rn(o[r][0]);
            __half h1 = __float2half_rn(o[r][1]);
            __half l0 = __float2half_rn(o[r][0] - __half2float(h0));
            __half l1 = __float2half_rn(o[r][1] - __half2float(h1));
            *(__half2*)dst         = __halves2half2(h0, h1);
            *(__half2*)(dst + 256) = __halves2half2(l0, l1);
        }
    }
}

// ---------------- host launcher ----------------
extern "C" void kernel_launch(void* const* d_in, const int* in_sizes, int n_in,
                              void* d_out, int out_size)
{
    const float* x          = (const float*)d_in[0];
    const float* rgb        = (const float*)d_in[1];
    const float* mask       = (const float*)d_in[2];
    const float* w_qkv      = (const float*)d_in[3];
    const float* b_qkv      = (const float*)d_in[4];
    const float* w_qkv_rgb  = (const float*)d_in[5];
    const float* b_qkv_rgb  = (const float*)d_in[6];
    const float* bias_table = (const float*)d_in[7];
    const float* w_proj     = (const float*)d_in[8];
    const float* b_proj     = (const float*)d_in[9];
    const float* w_proj_rgb = (const float*)d_in[10];
    const float* b_proj_rgb = (const float*)d_in[11];
    const int*   rel_idx    = (const int*)d_in[12];
    float* out = (float*)d_out;

    cudaFuncSetAttribute(qkv_hmma,  cudaFuncAttributeMaxDynamicSharedMemorySize, SMEM_SZ);
    cudaFuncSetAttribute(proj_hmma, cudaFuncAttributeMaxDynamicSharedMemorySize, SMEM_SZ);

    conv_w<<<dim3(768, 4), 256>>>(w_qkv, w_qkv_rgb, w_proj, w_proj_rgb);
    prep_bm<<<dim3(NW_, H_), 256>>>(mask, bias_table, rel_idx);
    conv_in<<<dim3(MT, 2), 256>>>(x, rgb);

    qkv_hmma<<<dim3(768 / BN, MT / BM, 2), 256, SMEM_SZ>>>(b_qkv, b_qkv_rgb);

    attn_kernel<<<dim3(B_, H_, 2), 192>>>();

    proj_hmma<<<dim3(256 / BN, MT / BM, 2), 256, SMEM_SZ>>>(b_proj, b_proj_rgb, out);
}